// round 15
// baseline (speedup 1.0000x reference)
#include <cuda_runtime.h>
#include <cuda_fp16.h>
#include <math.h>

#define BB 8
#define CC 64
#define NN 1000
#define TT 24
#define RR 10
#define NT 24000     // NN*TT
#define CT 1536      // CC*TT
#define NCO 64000    // NN*CC

// ------------------------- scratch (device globals, no allocs) -------------
__device__ float  g_x1t[BB*NN*CT];        // x1 transposed [b][n][(c*T+t)] fp32
__device__ __half g_x1h[BB*NN*CT];        // fp16 copy for GEMM B
__device__ __half g_Agh[BB*NN*NN];        // gated adjacency fp16 [b][n][m] row-major
__device__ __half g_AgT[BB*1008*NN];      // transposed [b][m(k) pad 1008][n]
__device__ float  g_g1[BB*NN*CT];         // Ag @ x1t  [b][n][(c*T+t)]
__device__ float g_s1a[BB*CC*RR];
__device__ float g_s2a[BB*RR*CC];
__device__ float g_att0[BB*CC*CC];
__device__ float g_s1g[BB*NN*RR];
__device__ float g_s2g[BB*RR*NN];
__device__ float g_s1t[BB*TT*RR];
__device__ float g_s2t[BB*RR*TT];
__device__ float g_attT[BB*TT*TT];
// transposed / fused weights
__device__ float g_a0W1T[RR*NT];
__device__ float g_gW1T[RR*CT];
__device__ float g_F1T[RR*NCO];
__device__ float g_F2T[RR*NCO];
__device__ float g_w1T[2*CC*CC];
__device__ float g_w2T[2*CC*CC];
__device__ float g_rT[CC*CC];
// half weights for k_final fast stages
__device__ __half g_gWh[CC*CC];           // gcn_W [c][o]
__device__ __half g_w1h[2*CC*CC];         // conv1 [tap][c][o]
__device__ __half g_w2h[2*CC*CC];         // conv2 [tap][c][o]

// ------------------------- f32x2 helpers -----------------------------------
__device__ __forceinline__ unsigned long long dup2(float v) {
    unsigned long long r; unsigned u = __float_as_uint(v);
    asm("mov.b64 %0, {%1, %1};" : "=l"(r) : "r"(u));
    return r;
}
__device__ __forceinline__ unsigned long long pack2(float lo, float hi) {
    unsigned long long r;
    asm("mov.b64 %0, {%1, %2};" : "=l"(r) : "r"(__float_as_uint(lo)), "r"(__float_as_uint(hi)));
    return r;
}
__device__ __forceinline__ void fma2(unsigned long long& d,
                                     unsigned long long a, unsigned long long b) {
    asm("fma.rn.f32x2 %0, %1, %2, %0;" : "+l"(d) : "l"(a), "l"(b));
}
__device__ __forceinline__ float lo32(unsigned long long v) {
    return __uint_as_float((unsigned)v);
}
__device__ __forceinline__ float hi32(unsigned long long v) {
    return __uint_as_float((unsigned)(v >> 32));
}

// ------------------------- K0: weight prep (transposes + half + pad) -------
__global__ void k_prep(const float* __restrict__ a0W1, const float* __restrict__ gW1,
                       const float* __restrict__ c1w, const float* __restrict__ c2w,
                       const float* __restrict__ rw, const float* __restrict__ gcnW) {
    int e = blockIdx.x * 256 + threadIdx.x;
    if (e < NT*RR)  { int k = e/RR, r = e - k*RR; g_a0W1T[r*NT + k] = a0W1[e]; return; }
    e -= NT*RR;
    if (e < CT*RR)  { int k = e/RR, r = e - k*RR; g_gW1T[r*CT + k] = gW1[e]; return; }
    e -= CT*RR;
    if (e < CC*CC) {
        int o = e >> 6, c = e & 63;
        float w10 = c1w[e*2 + 0], w11 = c1w[e*2 + 1];
        float w20 = c2w[e*2 + 0], w21 = c2w[e*2 + 1];
        g_w1T[c*CC + o]         = w10;
        g_w1T[CC*CC + c*CC + o] = w11;
        g_w2T[c*CC + o]         = w20;
        g_w2T[CC*CC + c*CC + o] = w21;
        g_rT[c*CC + o]          = rw[e];
        g_w1h[c*CC + o]         = __float2half_rn(w10);
        g_w1h[CC*CC + c*CC + o] = __float2half_rn(w11);
        g_w2h[c*CC + o]         = __float2half_rn(w20);
        g_w2h[CC*CC + c*CC + o] = __float2half_rn(w21);
        g_gWh[e]                = __float2half_rn(gcnW[e]);
        return;
    }
    e -= CC*CC;
    if (e < BB*8*NN) {                         // zero k-pad rows [1000,1008) of g_AgT
        int b = e / (8*NN); int rem = e - b*(8*NN);
        int row = 1000 + rem / NN, col = rem - (rem/NN)*NN;
        g_AgT[((size_t)b*1008 + row)*NN + col] = __float2half_rn(0.f);
    }
}

// ------------------------- K0b: fuse gcn_W into tatt weights ---------------
__global__ void k_fuse(const float* __restrict__ gcnW, const float* __restrict__ tW1,
                       const float* __restrict__ tW2) {
    int n = blockIdx.x;
    __shared__ float gs[CC*CC];
    __shared__ float w1s[CC*RR];
    __shared__ float w2s[RR*CC];
    int tid = threadIdx.x;
    for (int e = tid; e < CC*CC; e += 256) gs[e] = gcnW[e];
    for (int e = tid; e < CC*RR; e += 256) w1s[e] = tW1[(size_t)(n*CC)*RR + e];
    for (int e = tid; e < RR*CC; e += 256) {
        int r = e / CC, o = e - r*CC;
        w2s[e] = tW2[(size_t)r*NCO + n*CC + o];
    }
    __syncthreads();
    for (int idx = tid; idx < CC*RR; idx += 256) {
        int c = idx / RR, r = idx - c*RR;
        float s1 = 0.f, s2 = 0.f;
#pragma unroll 16
        for (int o = 0; o < CC; o++) {
            float g = gs[c*CC + o];
            s1 += g * w1s[o*RR + r];
            s2 += g * w2s[r*CC + o];
        }
        g_F1T[(size_t)r*NCO + n*CC + c] = s1;
        g_F2T[(size_t)r*NCO + n*CC + c] = s2;
    }
}

// ------------------------- K1: channel-attn projections (4 rows/block) -----
__global__ void __launch_bounds__(256) k_attA_proj(const float* __restrict__ x,
                                                   const float* __restrict__ W2) {
    int g0 = blockIdx.x * 4;
    float a1[4][RR], a2[4][RR];
#pragma unroll
    for (int j = 0; j < 4; j++)
#pragma unroll
        for (int r = 0; r < RR; r++) { a1[j][r] = 0.f; a2[j][r] = 0.f; }
    for (int k4 = threadIdx.x * 4; k4 < NT; k4 += 1024) {
        float4 xv[4];
#pragma unroll
        for (int j = 0; j < 4; j++)
            xv[j] = *(const float4*)(x + (size_t)(g0 + j)*NT + k4);
#pragma unroll
        for (int r = 0; r < RR; r++) {
            float4 w1 = *(const float4*)(g_a0W1T + r*NT + k4);
            float4 w2 = *(const float4*)(W2 + r*NT + k4);
#pragma unroll
            for (int j = 0; j < 4; j++) {
                a1[j][r] += xv[j].x*w1.x + xv[j].y*w1.y + xv[j].z*w1.z + xv[j].w*w1.w;
                a2[j][r] += xv[j].x*w2.x + xv[j].y*w2.y + xv[j].z*w2.z + xv[j].w*w2.w;
            }
        }
    }
    __shared__ float red[8][80];
    int lane = threadIdx.x & 31, warp = threadIdx.x >> 5;
#pragma unroll
    for (int j = 0; j < 4; j++)
#pragma unroll
        for (int r = 0; r < RR; r++) {
#pragma unroll
            for (int off = 16; off > 0; off >>= 1) {
                a1[j][r] += __shfl_down_sync(0xffffffffu, a1[j][r], off);
                a2[j][r] += __shfl_down_sync(0xffffffffu, a2[j][r], off);
            }
            if (lane == 0) { red[warp][j*RR + r] = a1[j][r]; red[warp][40 + j*RR + r] = a2[j][r]; }
        }
    __syncthreads();
    int tid = threadIdx.x;
    if (tid < 80) {
        float s = 0.f;
#pragma unroll
        for (int w = 0; w < 8; w++) s += red[w][tid];
        if (tid < 40) {
            int j = tid / RR, r = tid - j*RR;
            g_s1a[(g0 + j)*RR + r] = s;
        } else {
            int k = tid - 40;
            int j = k / RR, r = k - j*RR;
            int bc = g0 + j, b = bc >> 6, c = bc & 63;
            g_s2a[(b*RR + r)*CC + c] = s;
        }
    }
}

// ------------------------- K2: channel-attn softmax (64x64) ----------------
__global__ void k_attA_soft() {
    int b = blockIdx.x >> 6, i = blockIdx.x & 63;
    int j = threadIdx.x;
    float s = 0.f;
#pragma unroll
    for (int r = 0; r < RR; r++) s += g_s1a[(b*CC + i)*RR + r] * g_s2a[(b*RR + r)*CC + j];
    s *= rsqrtf((float)NT);
    __shared__ float sm[CC];
    sm[j] = s; __syncthreads();
    float mx = -1e30f;
    for (int jj = 0; jj < CC; jj++) mx = fmaxf(mx, sm[jj]);
    float e = expf(s - mx);
    __syncthreads();
    sm[j] = e; __syncthreads();
    float sum = 0.f;
    for (int jj = 0; jj < CC; jj++) sum += sm[jj];
    g_att0[(b*CC + i)*CC + j] = e / sum;
}

// ------------------------- K3: x1t = att0 @ xf (fp32 + fp16 copy) ----------
__global__ void __launch_bounds__(256) k_chan_apply(const float* __restrict__ x) {
    int b = blockIdx.y;
    int k0 = blockIdx.x * 64;
    __shared__ float atts[CC][68];
    __shared__ float xfs[CC][64];
    int tid = threadIdx.x;
    for (int e = tid; e < CC*CC; e += 256) {
        int c = e >> 6, j = e & 63;
        atts[j][c] = g_att0[b*CC*CC + e];
    }
    for (int e = tid; e < CC*64; e += 256) {
        int j = e >> 6, kk = e & 63;
        xfs[j][kk] = x[(size_t)(b*CC + j)*NT + k0 + kk];
    }
    __syncthreads();
    int tx = tid & 15, ty = tid >> 4;
    unsigned long long acc[4][2];
#pragma unroll
    for (int i = 0; i < 4; i++) { acc[i][0] = 0ull; acc[i][1] = 0ull; }
#pragma unroll 4
    for (int j = 0; j < CC; j++) {
        float4 a = *(const float4*)&atts[j][ty*4];
        ulonglong2 xv = *(const ulonglong2*)&xfs[j][tx*4];
        unsigned long long d0 = dup2(a.x), d1 = dup2(a.y), d2 = dup2(a.z), d3 = dup2(a.w);
        fma2(acc[0][0], d0, xv.x); fma2(acc[0][1], d0, xv.y);
        fma2(acc[1][0], d1, xv.x); fma2(acc[1][1], d1, xv.y);
        fma2(acc[2][0], d2, xv.x); fma2(acc[2][1], d2, xv.y);
        fma2(acc[3][0], d3, xv.x); fma2(acc[3][1], d3, xv.y);
    }
    int kk0 = k0 + tx*4;
    int n = kk0 / TT, t0 = kk0 - n*TT;
    size_t base = ((size_t)b*NN + n)*CT + t0;
#pragma unroll
    for (int ci = 0; ci < 4; ci++) {
        int c = ty*4 + ci;
        float vx = lo32(acc[ci][0]), vy = hi32(acc[ci][0]);
        float vz = lo32(acc[ci][1]), vw = hi32(acc[ci][1]);
        *(float4*)&g_x1t[base + c*TT] = make_float4(vx, vy, vz, vw);
        union { uint2 u; __half2 h[2]; } q;
        q.h[0] = __floats2half2_rn(vx, vy);
        q.h[1] = __floats2half2_rn(vz, vw);
        *(uint2*)&g_x1h[base + c*TT] = q.u;
    }
}

// ------------------------- K4: graph-attn projections (16 rows/block) ------
__global__ void __launch_bounds__(256) k_gatt_proj(const float* __restrict__ W2) {
    int base = blockIdx.x * 16;
    __shared__ float red[8][2*RR];
    int lane = threadIdx.x & 31, warp = threadIdx.x >> 5;
    for (int row = 0; row < 16; row++) {
        int bn = base + row;
        int b = bn / NN, n = bn - b*NN;
        const float* xf = g_x1t + (size_t)bn * CT;
        float a1[RR], a2[RR];
#pragma unroll
        for (int r = 0; r < RR; r++) { a1[r] = 0.f; a2[r] = 0.f; }
        for (int k4 = threadIdx.x * 4; k4 < CT; k4 += 1024) {
            float4 xv = *(const float4*)(xf + k4);
#pragma unroll
            for (int r = 0; r < RR; r++) {
                float4 w1 = *(const float4*)(g_gW1T + r*CT + k4);
                float4 w2 = *(const float4*)(W2 + r*CT + k4);
                a1[r] += xv.x*w1.x + xv.y*w1.y + xv.z*w1.z + xv.w*w1.w;
                a2[r] += xv.x*w2.x + xv.y*w2.y + xv.z*w2.z + xv.w*w2.w;
            }
        }
#pragma unroll
        for (int r = 0; r < RR; r++) {
#pragma unroll
            for (int off = 16; off > 0; off >>= 1) {
                a1[r] += __shfl_down_sync(0xffffffffu, a1[r], off);
                a2[r] += __shfl_down_sync(0xffffffffu, a2[r], off);
            }
        }
        if (lane == 0) {
#pragma unroll
            for (int r = 0; r < RR; r++) { red[warp][r] = a1[r]; red[warp][RR+r] = a2[r]; }
        }
        __syncthreads();
        if (threadIdx.x < 2*RR) {
            float s = 0.f;
#pragma unroll
            for (int w = 0; w < 8; w++) s += red[w][threadIdx.x];
            if (threadIdx.x < RR) g_s1g[(size_t)bn*RR + threadIdx.x] = s;
            else                  g_s2g[((size_t)b*RR + (threadIdx.x - RR))*NN + n] = s;
        }
        __syncthreads();
    }
}

// ------------------------- K5: graph softmax * A_adj (no-max, fp16 out) ----
__global__ void k_gatt_soft(const float* __restrict__ A_adj) {
    int bi = blockIdx.x;
    int b = bi / NN, i = bi - b*NN;
    __shared__ float sc[NN];
    __shared__ float s1r[RR];
    __shared__ float red[256];
    int tid = threadIdx.x;
    if (tid < RR) s1r[tid] = g_s1g[(size_t)(b*NN + i)*RR + tid];
    __syncthreads();
    float scale = rsqrtf((float)CT);
    float lsum = 0.f;
    for (int j = tid; j < NN; j += 256) {
        float s = 0.f;
#pragma unroll
        for (int r = 0; r < RR; r++) s += s1r[r] * g_s2g[(size_t)(b*RR + r)*NN + j];
        float e = expf(s * scale);
        sc[j] = e;
        lsum += e;
    }
    red[tid] = lsum; __syncthreads();
    for (int off = 128; off > 0; off >>= 1) {
        if (tid < off) red[tid] += red[tid + off];
        __syncthreads();
    }
    float inv = 1.f / red[0];
    for (int j = tid; j < NN; j += 256) {
        g_Agh[((size_t)b*NN + i)*NN + j] = __float2half_rn(sc[j] * inv * A_adj[i*NN + j]);
    }
}

// ------------------------- K5b: transpose Ag (row-major -> [k][n]) ---------
__global__ void __launch_bounds__(256) k_AgT() {
    int b  = blockIdx.z;
    int i0 = blockIdx.y * 64;   // source rows (n)
    int j0 = blockIdx.x * 64;   // source cols (m = k)
    __shared__ __half ts[64][72];
    int tid = threadIdx.x;
#pragma unroll
    for (int p = 0; p < 2; p++) {
        int ch = tid + p*256;
        int r = ch >> 3, c8 = (ch & 7) * 8;
        int i = i0 + r, j = j0 + c8;
        if (i < NN && j + 8 <= NN) {
            uint4 v = *(const uint4*)(g_Agh + ((size_t)b*NN + i)*NN + j);
            const __half* hp = (const __half*)&v;
#pragma unroll
            for (int q = 0; q < 8; q++) ts[c8 + q][r] = hp[q];
        }
    }
    __syncthreads();
#pragma unroll
    for (int p = 0; p < 2; p++) {
        int ch = tid + p*256;
        int r = ch >> 3, c8 = (ch & 7) * 8;
        int j = j0 + r;             // out row (k)
        int i = i0 + c8;            // out col (n)
        if (j < NN && i + 8 <= NN) {
            uint4 v;
            __half* hp = (__half*)&v;
#pragma unroll
            for (int q = 0; q < 8; q++) hp[q] = ts[r][c8 + q];
            *(uint4*)(g_AgT + ((size_t)b*1008 + j)*NN + i) = v;
        }
    }
}

// ------------------------- K7: big GEMM g1 = AgT^T @ x1t (HFMA2) -----------
#define GTM 128
#define GTN 128
#define GTK 16
__global__ void __launch_bounds__(256, 2) k_gemm() {
    int b  = blockIdx.z;
    int n0 = blockIdx.y * GTM;
    int j0 = blockIdx.x * GTN;
    const __half* A  = g_AgT + (size_t)b*1008*NN;   // [k][n]
    const __half* Bm = g_x1h + (size_t)b*NN*CT;     // [k][j]
    float*        Cm = g_g1  + (size_t)b*NN*CT;
    __shared__ __half As[2][GTK][GTM + 8];
    __shared__ __half Bs[2][GTK][GTN + 8];
    int tid = threadIdx.x;
    int tx = tid & 15, ty = tid >> 4;
    int arow = tid >> 4, acol = (tid & 15) * 8;     // A: k-row, n-col chunk
    int bk = tid >> 4, bj = (tid & 15) * 8;         // B: k-row, j-col chunk
    const uint4 z4 = make_uint4(0u, 0u, 0u, 0u);

    __half2 acch[8][4];
    float accf[8][8];
#pragma unroll
    for (int i = 0; i < 8; i++) {
#pragma unroll
        for (int j = 0; j < 4; j++) acch[i][j] = __float2half2_rn(0.f);
#pragma unroll
        for (int j = 0; j < 8; j++) accf[i][j] = 0.f;
    }

    const int NKT = (NN + GTK - 1) / GTK;      // 63 (k <= 1007 < 1008 pad)
    bool va_col = (n0 + acol < NN);            // col chunk validity (8-aligned)
    {
        uint4 av = va_col ? *(const uint4*)(A + (size_t)arow*NN + n0 + acol) : z4;
        *(uint4*)&As[0][arow][acol] = av;
        *(uint4*)&Bs[0][bk][bj] = *(const uint4*)(Bm + (size_t)bk*CT + j0 + bj);
    }
    __syncthreads();

    for (int kt = 0; kt < NKT; kt++) {
        int buf = kt & 1;
        uint4 av, bv;
        bool have_next = (kt + 1 < NKT);
        if (have_next) {
            int k0 = (kt + 1) * GTK;
            av = va_col ? *(const uint4*)(A + (size_t)(k0 + arow)*NN + n0 + acol) : z4;
            bool vb = (k0 + bk < NN);
            bv = vb ? *(const uint4*)(Bm + (size_t)(k0 + bk)*CT + j0 + bj) : z4;
        }
#pragma unroll
        for (int kk = 0; kk < GTK; kk++) {
            uint4 ar = *(const uint4*)&As[buf][kk][ty*8];
            uint4 br = *(const uint4*)&Bs[buf][kk][tx*8];
            const __half*  a8 = (const __half*)&ar;
            const __half2* b2 = (const __half2*)&br;
#pragma unroll
            for (int i = 0; i < 8; i++) {
                __half2 ad = __half2half2(a8[i]);
                acch[i][0] = __hfma2(ad, b2[0], acch[i][0]);
                acch[i][1] = __hfma2(ad, b2[1], acch[i][1]);
                acch[i][2] = __hfma2(ad, b2[2], acch[i][2]);
                acch[i][3] = __hfma2(ad, b2[3], acch[i][3]);
            }
        }
        if ((kt & 3) == 3 || kt == NKT - 1) {
#pragma unroll
            for (int i = 0; i < 8; i++)
#pragma unroll
                for (int j = 0; j < 4; j++) {
                    float2 f = __half22float2(acch[i][j]);
                    accf[i][2*j]   += f.x;
                    accf[i][2*j+1] += f.y;
                    acch[i][j] = __float2half2_rn(0.f);
                }
        }
        if (have_next) {
            int nb = buf ^ 1;
            *(uint4*)&As[nb][arow][acol] = av;
            *(uint4*)&Bs[nb][bk][bj] = bv;
        }
        __syncthreads();
    }
#pragma unroll
    for (int i = 0; i < 8; i++) {
        int n = n0 + ty*8 + i;
        if (n < NN) {
            float* cp = Cm + (size_t)n*CT + j0 + tx*8;
            *(float4*)cp       = make_float4(accf[i][0], accf[i][1], accf[i][2], accf[i][3]);
            *(float4*)(cp + 4) = make_float4(accf[i][4], accf[i][5], accf[i][6], accf[i][7]);
        }
    }
}

// ------------------------- K8: temporal-attn projections (r-split, 96 blk) -
__global__ void __launch_bounds__(256) k_tatt_proj() {
    int z  = blockIdx.x;
    int rh = z & 1;
    int bt = z >> 1;
    int b  = bt / 6;
    int tg = bt - b*6;
    int t0 = tg * 4;
    const float* g1b = g_g1 + (size_t)b*NN*CT;
    unsigned long long a1p[2][5], a2p[2][5];
#pragma unroll
    for (int p = 0; p < 2; p++)
#pragma unroll
        for (int r = 0; r < 5; r++) { a1p[p][r] = 0ull; a2p[p][r] = 0ull; }

    for (int i4 = threadIdx.x * 4; i4 < NCO; i4 += 1024) {
        int n = i4 >> 6, c0 = i4 & 63;
        const float* gp = g1b + (size_t)n*CT + c0*TT + t0;
        unsigned long long gq[4][2];
#pragma unroll
        for (int j = 0; j < 4; j++) {
            ulonglong2 gv = *(const ulonglong2*)(gp + j*TT);
            gq[j][0] = gv.x; gq[j][1] = gv.y;
        }
#pragma unroll
        for (int r = 0; r < 5; r++) {
            int rr = rh*5 + r;
            float4 f1 = *(const float4*)(g_F1T + (size_t)rr*NCO + i4);
            float4 f2 = *(const float4*)(g_F2T + (size_t)rr*NCO + i4);
            unsigned long long d;
            d = dup2(f1.x); fma2(a1p[0][r], d, gq[0][0]); fma2(a1p[1][r], d, gq[0][1]);
            d = dup2(f1.y); fma2(a1p[0][r], d, gq[1][0]); fma2(a1p[1][r], d, gq[1][1]);
            d = dup2(f1.z); fma2(a1p[0][r], d, gq[2][0]); fma2(a1p[1][r], d, gq[2][1]);
            d = dup2(f1.w); fma2(a1p[0][r], d, gq[3][0]); fma2(a1p[1][r], d, gq[3][1]);
            d = dup2(f2.x); fma2(a2p[0][r], d, gq[0][0]); fma2(a2p[1][r], d, gq[0][1]);
            d = dup2(f2.y); fma2(a2p[0][r], d, gq[1][0]); fma2(a2p[1][r], d, gq[1][1]);
            d = dup2(f2.z); fma2(a2p[0][r], d, gq[2][0]); fma2(a2p[1][r], d, gq[2][1]);
            d = dup2(f2.w); fma2(a2p[0][r], d, gq[3][0]); fma2(a2p[1][r], d, gq[3][1]);
        }
    }
    __shared__ unsigned long long redu[8][20];
    int lane = threadIdx.x & 31, warp = threadIdx.x >> 5;
#pragma unroll
    for (int p = 0; p < 2; p++)
#pragma unroll
        for (int r = 0; r < 5; r++) {
            unsigned long long v1 = a1p[p][r], v2 = a2p[p][r];
#pragma unroll
            for (int off = 16; off > 0; off >>= 1) {
                float l1 = lo32(v1) + __shfl_down_sync(0xffffffffu, lo32(v1), off);
                float h1 = hi32(v1) + __shfl_down_sync(0xffffffffu, hi32(v1), off);
                float l2 = lo32(v2) + __shfl_down_sync(0xffffffffu, lo32(v2), off);
                float h2 = hi32(v2) + __shfl_down_sync(0xffffffffu, hi32(v2), off);
                v1 = pack2(l1, h1); v2 = pack2(l2, h2);
            }
            if (lane == 0) {
                redu[warp][r*2 + p]      = v1;
                redu[warp][10 + r*2 + p] = v2;
            }
        }
    __syncthreads();
    int tid = threadIdx.x;
    if (tid < 20) {
        float slo = 0.f, shi = 0.f;
#pragma unroll
        for (int w = 0; w < 8; w++) {
            unsigned long long v = redu[w][tid];
            slo += lo32(v); shi += hi32(v);
        }
        int mat = tid / 10;
        int rem = tid - mat*10;
        int r = rem >> 1, p = rem & 1;
        int rr = rh*5 + r;
        int t = t0 + 2*p;
        if (mat == 0) {
            g_s1t[(b*TT + t)*RR + rr]     = slo;
            g_s1t[(b*TT + t + 1)*RR + rr] = shi;
        } else {
            g_s2t[(b*RR + rr)*TT + t]     = slo;
            g_s2t[(b*RR + rr)*TT + t + 1] = shi;
        }
    }
}

// ------------------------- K9: temporal softmax (24x24) --------------------
__global__ void k_tatt_soft() {
    int b = blockIdx.x;
    int i = threadIdx.x;
    if (i >= TT) return;
    float sc[TT];
    float scale = rsqrtf((float)NCO);
#pragma unroll
    for (int j = 0; j < TT; j++) {
        float s = 0.f;
#pragma unroll
        for (int r = 0; r < RR; r++) s += g_s1t[(b*TT + i)*RR + r] * g_s2t[(b*RR + r)*TT + j];
        sc[j] = s * scale;
    }
    float mx = -1e30f;
#pragma unroll
    for (int j = 0; j < TT; j++) mx = fmaxf(mx, sc[j]);
    float sum = 0.f;
#pragma unroll
    for (int j = 0; j < TT; j++) { sc[j] = expf(sc[j] - mx); sum += sc[j]; }
    float inv = 1.f / sum;
#pragma unroll
    for (int j = 0; j < TT; j++) g_attT[(b*TT + i)*TT + j] = sc[j] * inv;
}

// ------------------------- K10: fused mix+tatt+convs (half2) + res+LN (f32) -
__global__ void __launch_bounds__(256) k_final(
        const float* __restrict__ x,
        const float* __restrict__ c1b,
        const float* __restrict__ c2b,
        const float* __restrict__ rb,
        const float* __restrict__ lng,
        const float* __restrict__ lnb,
        float* __restrict__ out) {
    __shared__ float smB[4*CT];
    __shared__ __half at_h[TT*TT];
    __shared__ float mu_s[4][TT], rs_s[4][TT];
    __half* smH = (__half*)smB;
    int blk = blockIdx.x;
    int b = blk / 250;
    int n0 = (blk - b*250) * 4;
    int tid = threadIdx.x;
    int u = tid >> 6, o = tid & 63;
    int n = n0 + u;
    const __half2 hz = __float2half2_rn(0.f);

    {
        const float* src = g_g1 + ((size_t)b*NN + n0)*CT;
        for (int e4 = tid; e4 < CT; e4 += 256) {
            float4 v = *(const float4*)(src + e4*4);
            union { uint2 u2; __half2 h[2]; } q;
            q.h[0] = __floats2half2_rn(v.x, v.y);
            q.h[1] = __floats2half2_rn(v.z, v.w);
            *(uint2*)&smH[e4*4] = q.u2;
        }
    }
    for (int e = tid; e < TT*TT; e += 256) {
        int t = e / TT, tp = e - t*TT;
        at_h[tp*TT + t] = __float2half_rn(g_attT[b*TT*TT + e]);
    }
    __syncthreads();

    __half2 gmp[12];
#pragma unroll
    for (int k = 0; k < 12; k++) gmp[k] = hz;
#pragma unroll 4
    for (int c = 0; c < CC; c++) {
        __half2 wd = __half2half2(g_gWh[c*CC + o]);
        const __half2* pr = (const __half2*)(smH + u*CT + c*TT);
#pragma unroll
        for (int k = 0; k < 12; k++) gmp[k] = __hfma2(wd, pr[k], gmp[k]);
    }

    __half2 x2p[12];
#pragma unroll
    for (int k = 0; k < 12; k++) x2p[k] = hz;
#pragma unroll 4
    for (int tp = 0; tp < TT; tp++) {
        __half gv = (tp & 1) ? __high2half(gmp[tp >> 1]) : __low2half(gmp[tp >> 1]);
        __half2 gd = __half2half2(gv);
        const __half2* ar = (const __half2*)(at_h + tp*TT);
#pragma unroll
        for (int k = 0; k < 12; k++) x2p[k] = __hfma2(gd, ar[k], x2p[k]);
    }
    __syncthreads();
    {
        __half2* wp = (__half2*)(smH + u*CT + o*TT);
#pragma unroll
        for (int k = 0; k < 12; k++) wp[k] = x2p[k];
    }
    __syncthreads();

    __half2 yp[12];
#pragma unroll
    for (int k = 0; k < 12; k++) yp[k] = hz;
#pragma unroll 4
    for (int c = 0; c < CC; c++) {
        const __half2* pr = (const __half2*)(smH + u*CT + c*TT);
        __half2 w0d = __half2half2(g_w1h[c*CC + o]);
        __half2 w1d = __half2half2(g_w1h[CC*CC + c*CC + o]);
        __half2 tp_[12];
#pragma unroll
        for (int k = 0; k < 12; k++) tp_[k] = pr[k];
#pragma unroll
        for (int k = 0; k < 12; k++) yp[k] = __hfma2(w1d, tp_[k], yp[k]);
        __half2 sh = __halves2half2(__float2half_rn(0.f), __low2half(tp_[0]));
        yp[0] = __hfma2(w0d, sh, yp[0]);
#pragma unroll
        for (int k = 1; k < 12; k++) {
            sh = __halves2half2(__high2half(tp_[k-1]), __low2half(tp_[k]));
            yp[k] = __hfma2(w0d, sh, yp[k]);
        }
    }
    __half2 y1h[12];
    {
        float b1 = __ldg(c1b + o);
#pragma unroll
        for (int k = 0; k < 12; k++) {
            float2 f = __half22float2(yp[k]);
            y1h[k] = __floats2half2_rn(fmaxf(f.x + b1, 0.f), fmaxf(f.y + b1, 0.f));
        }
    }
    __syncthreads();
    {
        __half2* wp = (__half2*)(smH + u*CT + o*TT);
#pragma unroll
        for (int k = 0; k < 12; k++) wp[k] = y1h[k];
    }
    __syncthreads();

    __half2 vph[12];
#pragma unroll
    for (int k = 0; k < 12; k++) vph[k] = hz;
#pragma unroll 4
    for (int c = 0; c < CC; c++) {
        const __half2* pr = (const __half2*)(smH + u*CT + c*TT);
        __half2 w0d = __half2half2(g_w2h[c*CC + o]);
        __half2 w1d = __half2half2(g_w2h[CC*CC + c*CC + o]);
        __half2 prev = hz;
#pragma unroll
        for (int k = 0; k < 12; k++) {
            __half2 cur = pr[k];
            vph[k] = __hfma2(w1d, cur, vph[k]);
            vph[k] = __hfma2(w0d, prev, vph[k]);
            prev = cur;
        }
    }
    float v[TT];
    {
        float b2 = __ldg(c2b + o);
#pragma unroll
        for (int k = 0; k < 12; k++) {
            float2 f = __half22float2(vph[k]);
            v[2*k]   = fmaxf(f.x + b2, 0.f);
            v[2*k+1] = fmaxf(f.y + b2, 0.f);
        }
    }
    __syncthreads();

    for (int e4 = tid; e4 < CT; e4 += 256) {
        int f = e4 * 4;
        int u2 = f / CT, rem = f - u2*CT;
        int c = rem / TT, t = rem - c*TT;
        *(float4*)&smB[f] = *(const float4*)(x + (size_t)((b*CC + c)*NN + n0 + u2)*TT + t);
    }
    __syncthreads();

    unsigned long long vp[12];
#pragma unroll
    for (int k = 0; k < 12; k++) vp[k] = pack2(v[2*k], v[2*k+1]);
#pragma unroll 4
    for (int c = 0; c < CC; c++) {
        const unsigned long long* pr = (const unsigned long long*)&smB[u*CT + c*TT];
        unsigned long long rwd = dup2(__ldg(g_rT + c*CC + o));
#pragma unroll
        for (int k = 0; k < 12; k++) fma2(vp[k], rwd, pr[k]);
    }
    {
        float biasr = __ldg(rb + o);
#pragma unroll
        for (int k = 0; k < 12; k++) {
            float lo = fmaxf(lo32(vp[k]) + biasr, 0.f);
            float hi = fmaxf(hi32(vp[k]) + biasr, 0.f);
            v[2*k] = lo; v[2*k+1] = hi;
        }
    }
    __syncthreads();

    {
        float* wp = &smB[u*CT + o*TT];
#pragma unroll
        for (int k = 0; k < 6; k++)
            *(float4*)(wp + 4*k) = make_float4(v[4*k], v[4*k+1], v[4*k+2], v[4*k+3]);
    }
    __syncthreads();
    if (tid < 96) {
        int ur = tid / TT, tr = tid - ur*TT;
        float S = 0.f, Q = 0.f;
#pragma unroll 8
        for (int oo = 0; oo < CC; oo++) {
            float val = smB[ur*CT + oo*TT + tr];
            S += val; Q += val*val;
        }
        float mu = S * (1.f/CC);
        float var = Q * (1.f/CC) - mu*mu;
        mu_s[ur][tr] = mu;
        rs_s[ur][tr] = rsqrtf(var + 1e-5f);
    }
    __syncthreads();
    {
        float gmul = __ldg(lng + o), badd = __ldg(lnb + o);
        float* op = out + (size_t)((b*CC + o)*NN + n)*TT;
        float res[TT];
#pragma unroll
        for (int t = 0; t < TT; t++)
            res[t] = (v[t] - mu_s[u][t]) * rs_s[u][t] * gmul + badd;
#pragma unroll
        for (int k = 0; k < 6; k++)
            *(float4*)(op + 4*k) = make_float4(res[4*k], res[4*k+1], res[4*k+2], res[4*k+3]);
    }
}

// ------------------------- launch ------------------------------------------
extern "C" void kernel_launch(void* const* d_in, const int* in_sizes, int n_in,
                              void* d_out, int out_size) {
    const float* x     = (const float*)d_in[0];
    const float* A_adj = (const float*)d_in[1];
    const float* a0W1  = (const float*)d_in[2];
    const float* a0W2  = (const float*)d_in[3];
    const float* gW1   = (const float*)d_in[4];
    const float* gW2   = (const float*)d_in[5];
    const float* gcnW  = (const float*)d_in[6];
    const float* tW1   = (const float*)d_in[7];
    const float* tW2   = (const float*)d_in[8];
    const float* c1w   = (const float*)d_in[9];
    const float* c1b   = (const float*)d_in[10];
    const float* c2w   = (const float*)d_in[11];
    const float* c2b   = (const float*)d_in[12];
    const float* resw  = (const float*)d_in[13];
    const float* resb  = (const float*)d_in[14];
    const float* lng   = (const float*)d_in[15];
    const float* lnb   = (const float*)d_in[16];
    float* out = (float*)d_out;

    // prep elems: NT*RR + CT*RR + CC*CC + AgT k-pad (BB*8*NN)
    const int prep_elems = NT*RR + CT*RR + CC*CC + BB*8*NN;
    k_prep<<<(prep_elems + 255)/256, 256>>>(a0W1, gW1, c1w, c2w, resw, gcnW);
    k_fuse<<<NN, 256>>>(gcnW, tW1, tW2);
    k_attA_proj<<<BB*CC/4, 256>>>(x, a0W2);
    k_attA_soft<<<BB*CC, CC>>>();
    k_chan_apply<<<dim3(NT/64, BB), 256>>>(x);
    k_gatt_proj<<<BB*NN/16, 256>>>(gW2);
    k_gatt_soft<<<BB*NN, 256>>>(A_adj);
    k_AgT<<<dim3(16, 16, BB), 256>>>();
    k_gemm<<<dim3(CT/GTN, (NN + GTM - 1)/GTM, BB), 256>>>();
    k_tatt_proj<<<BB*6*2, 256>>>();
    k_tatt_soft<<<BB, 32>>>();
    k_final<<<BB*NN/4, 256>>>(x, c1b, c2b, resb, lng, lnb, out);
}

// round 17
// speedup vs baseline: 1.0081x; 1.0081x over previous
#include <cuda_runtime.h>
#include <cuda_fp16.h>
#include <math.h>

#define BB 8
#define CC 64
#define NN 1000
#define TT 24
#define RR 10
#define NT 24000     // NN*TT
#define CT 1536      // CC*TT
#define NCO 64000    // NN*CC

// ------------------------- scratch (device globals, no allocs) -------------
__device__ float  g_x1t[BB*NN*CT];        // x1 transposed [b][n][(c*T+t)] fp32
__device__ __half g_x1h[BB*NN*CT];        // fp16 copy for GEMM B
__device__ __half g_Agh[BB*NN*NN];        // gated adjacency fp16 [b][n][m]
__device__ float  g_g1[BB*NN*CT];         // Ag @ x1t  [b][n][(c*T+t)]
__device__ float g_s1a[BB*CC*RR];
__device__ float g_s2a[BB*RR*CC];
__device__ float g_att0[BB*CC*CC];
__device__ float g_s1g[BB*NN*RR];
__device__ float g_s2g[BB*RR*NN];
__device__ float g_s1t[BB*TT*RR];
__device__ float g_s2t[BB*RR*TT];
__device__ float g_attT[BB*TT*TT];
// transposed / fused weights
__device__ float g_a0W1T[RR*NT];
__device__ float g_gW1T[RR*CT];
__device__ float g_F1T[RR*NCO];
__device__ float g_F2T[RR*NCO];
__device__ float g_w1T[2*CC*CC];
__device__ float g_w2T[2*CC*CC];
__device__ float g_rT[CC*CC];
// half weights for k_final fast stages
__device__ __half g_gWh[CC*CC];           // gcn_W [c][o]
__device__ __half g_w1h[2*CC*CC];         // conv1 [tap][c][o]
__device__ __half g_w2h[2*CC*CC];         // conv2 [tap][c][o]

// ------------------------- f32x2 helpers -----------------------------------
__device__ __forceinline__ unsigned long long dup2(float v) {
    unsigned long long r; unsigned u = __float_as_uint(v);
    asm("mov.b64 %0, {%1, %1};" : "=l"(r) : "r"(u));
    return r;
}
__device__ __forceinline__ unsigned long long pack2(float lo, float hi) {
    unsigned long long r;
    asm("mov.b64 %0, {%1, %2};" : "=l"(r) : "r"(__float_as_uint(lo)), "r"(__float_as_uint(hi)));
    return r;
}
__device__ __forceinline__ void fma2(unsigned long long& d,
                                     unsigned long long a, unsigned long long b) {
    asm("fma.rn.f32x2 %0, %1, %2, %0;" : "+l"(d) : "l"(a), "l"(b));
}
__device__ __forceinline__ float lo32(unsigned long long v) {
    return __uint_as_float((unsigned)v);
}
__device__ __forceinline__ float hi32(unsigned long long v) {
    return __uint_as_float((unsigned)(v >> 32));
}

// ------------------------- K0: weight prep (transposes + half) -------------
__global__ void k_prep(const float* __restrict__ a0W1, const float* __restrict__ gW1,
                       const float* __restrict__ c1w, const float* __restrict__ c2w,
                       const float* __restrict__ rw, const float* __restrict__ gcnW) {
    int e = blockIdx.x * 256 + threadIdx.x;
    if (e < NT*RR)  { int k = e/RR, r = e - k*RR; g_a0W1T[r*NT + k] = a0W1[e]; return; }
    e -= NT*RR;
    if (e < CT*RR)  { int k = e/RR, r = e - k*RR; g_gW1T[r*CT + k] = gW1[e]; return; }
    e -= CT*RR;
    if (e < CC*CC) {
        int o = e >> 6, c = e & 63;
        float w10 = c1w[e*2 + 0], w11 = c1w[e*2 + 1];
        float w20 = c2w[e*2 + 0], w21 = c2w[e*2 + 1];
        g_w1T[c*CC + o]         = w10;
        g_w1T[CC*CC + c*CC + o] = w11;
        g_w2T[c*CC + o]         = w20;
        g_w2T[CC*CC + c*CC + o] = w21;
        g_rT[c*CC + o]          = rw[e];
        g_w1h[c*CC + o]         = __float2half_rn(w10);
        g_w1h[CC*CC + c*CC + o] = __float2half_rn(w11);
        g_w2h[c*CC + o]         = __float2half_rn(w20);
        g_w2h[CC*CC + c*CC + o] = __float2half_rn(w21);
        g_gWh[e]                = __float2half_rn(gcnW[e]);
    }
}

// ------------------------- K0b: fuse gcn_W into tatt weights ---------------
__global__ void k_fuse(const float* __restrict__ gcnW, const float* __restrict__ tW1,
                       const float* __restrict__ tW2) {
    int n = blockIdx.x;
    __shared__ float gs[CC*CC];
    __shared__ float w1s[CC*RR];
    __shared__ float w2s[RR*CC];
    int tid = threadIdx.x;
    for (int e = tid; e < CC*CC; e += 256) gs[e] = gcnW[e];
    for (int e = tid; e < CC*RR; e += 256) w1s[e] = tW1[(size_t)(n*CC)*RR + e];
    for (int e = tid; e < RR*CC; e += 256) {
        int r = e / CC, o = e - r*CC;
        w2s[e] = tW2[(size_t)r*NCO + n*CC + o];
    }
    __syncthreads();
    for (int idx = tid; idx < CC*RR; idx += 256) {
        int c = idx / RR, r = idx - c*RR;
        float s1 = 0.f, s2 = 0.f;
#pragma unroll 16
        for (int o = 0; o < CC; o++) {
            float g = gs[c*CC + o];
            s1 += g * w1s[o*RR + r];
            s2 += g * w2s[r*CC + o];
        }
        g_F1T[(size_t)r*NCO + n*CC + c] = s1;
        g_F2T[(size_t)r*NCO + n*CC + c] = s2;
    }
}

// ------------------------- K1: channel-attn projections (4 rows/block) -----
__global__ void __launch_bounds__(256) k_attA_proj(const float* __restrict__ x,
                                                   const float* __restrict__ W2) {
    int g0 = blockIdx.x * 4;
    float a1[4][RR], a2[4][RR];
#pragma unroll
    for (int j = 0; j < 4; j++)
#pragma unroll
        for (int r = 0; r < RR; r++) { a1[j][r] = 0.f; a2[j][r] = 0.f; }
    for (int k4 = threadIdx.x * 4; k4 < NT; k4 += 1024) {
        float4 xv[4];
#pragma unroll
        for (int j = 0; j < 4; j++)
            xv[j] = *(const float4*)(x + (size_t)(g0 + j)*NT + k4);
#pragma unroll
        for (int r = 0; r < RR; r++) {
            float4 w1 = *(const float4*)(g_a0W1T + r*NT + k4);
            float4 w2 = *(const float4*)(W2 + r*NT + k4);
#pragma unroll
            for (int j = 0; j < 4; j++) {
                a1[j][r] += xv[j].x*w1.x + xv[j].y*w1.y + xv[j].z*w1.z + xv[j].w*w1.w;
                a2[j][r] += xv[j].x*w2.x + xv[j].y*w2.y + xv[j].z*w2.z + xv[j].w*w2.w;
            }
        }
    }
    __shared__ float red[8][80];
    int lane = threadIdx.x & 31, warp = threadIdx.x >> 5;
#pragma unroll
    for (int j = 0; j < 4; j++)
#pragma unroll
        for (int r = 0; r < RR; r++) {
#pragma unroll
            for (int off = 16; off > 0; off >>= 1) {
                a1[j][r] += __shfl_down_sync(0xffffffffu, a1[j][r], off);
                a2[j][r] += __shfl_down_sync(0xffffffffu, a2[j][r], off);
            }
            if (lane == 0) { red[warp][j*RR + r] = a1[j][r]; red[warp][40 + j*RR + r] = a2[j][r]; }
        }
    __syncthreads();
    int tid = threadIdx.x;
    if (tid < 80) {
        float s = 0.f;
#pragma unroll
        for (int w = 0; w < 8; w++) s += red[w][tid];
        if (tid < 40) {
            int j = tid / RR, r = tid - j*RR;
            g_s1a[(g0 + j)*RR + r] = s;
        } else {
            int k = tid - 40;
            int j = k / RR, r = k - j*RR;
            int bc = g0 + j, b = bc >> 6, c = bc & 63;
            g_s2a[(b*RR + r)*CC + c] = s;
        }
    }
}

// ------------------------- K2: channel-attn softmax (64x64) ----------------
__global__ void k_attA_soft() {
    int b = blockIdx.x >> 6, i = blockIdx.x & 63;
    int j = threadIdx.x;
    float s = 0.f;
#pragma unroll
    for (int r = 0; r < RR; r++) s += g_s1a[(b*CC + i)*RR + r] * g_s2a[(b*RR + r)*CC + j];
    s *= rsqrtf((float)NT);
    __shared__ float sm[CC];
    sm[j] = s; __syncthreads();
    float mx = -1e30f;
    for (int jj = 0; jj < CC; jj++) mx = fmaxf(mx, sm[jj]);
    float e = expf(s - mx);
    __syncthreads();
    sm[j] = e; __syncthreads();
    float sum = 0.f;
    for (int jj = 0; jj < CC; jj++) sum += sm[jj];
    g_att0[(b*CC + i)*CC + j] = e / sum;
}

// ------------------------- K3: x1t = att0 @ xf (fp32 + fp16 copy) ----------
__global__ void __launch_bounds__(256) k_chan_apply(const float* __restrict__ x) {
    int b = blockIdx.y;
    int k0 = blockIdx.x * 64;
    __shared__ float atts[CC][68];
    __shared__ float xfs[CC][64];
    int tid = threadIdx.x;
    for (int e = tid; e < CC*CC; e += 256) {
        int c = e >> 6, j = e & 63;
        atts[j][c] = g_att0[b*CC*CC + e];
    }
    for (int e = tid; e < CC*64; e += 256) {
        int j = e >> 6, kk = e & 63;
        xfs[j][kk] = x[(size_t)(b*CC + j)*NT + k0 + kk];
    }
    __syncthreads();
    int tx = tid & 15, ty = tid >> 4;
    unsigned long long acc[4][2];
#pragma unroll
    for (int i = 0; i < 4; i++) { acc[i][0] = 0ull; acc[i][1] = 0ull; }
#pragma unroll 4
    for (int j = 0; j < CC; j++) {
        float4 a = *(const float4*)&atts[j][ty*4];
        ulonglong2 xv = *(const ulonglong2*)&xfs[j][tx*4];
        unsigned long long d0 = dup2(a.x), d1 = dup2(a.y), d2 = dup2(a.z), d3 = dup2(a.w);
        fma2(acc[0][0], d0, xv.x); fma2(acc[0][1], d0, xv.y);
        fma2(acc[1][0], d1, xv.x); fma2(acc[1][1], d1, xv.y);
        fma2(acc[2][0], d2, xv.x); fma2(acc[2][1], d2, xv.y);
        fma2(acc[3][0], d3, xv.x); fma2(acc[3][1], d3, xv.y);
    }
    int kk0 = k0 + tx*4;
    int n = kk0 / TT, t0 = kk0 - n*TT;
    size_t base = ((size_t)b*NN + n)*CT + t0;
#pragma unroll
    for (int ci = 0; ci < 4; ci++) {
        int c = ty*4 + ci;
        float vx = lo32(acc[ci][0]), vy = hi32(acc[ci][0]);
        float vz = lo32(acc[ci][1]), vw = hi32(acc[ci][1]);
        *(float4*)&g_x1t[base + c*TT] = make_float4(vx, vy, vz, vw);
        union { uint2 u; __half2 h[2]; } q;
        q.h[0] = __floats2half2_rn(vx, vy);
        q.h[1] = __floats2half2_rn(vz, vw);
        *(uint2*)&g_x1h[base + c*TT] = q.u;
    }
}

// ------------------------- K4: graph-attn projections (16 rows/block) ------
__global__ void __launch_bounds__(256) k_gatt_proj(const float* __restrict__ W2) {
    int base = blockIdx.x * 16;
    __shared__ float red[8][2*RR];
    int lane = threadIdx.x & 31, warp = threadIdx.x >> 5;
    for (int row = 0; row < 16; row++) {
        int bn = base + row;
        int b = bn / NN, n = bn - b*NN;
        const float* xf = g_x1t + (size_t)bn * CT;
        float a1[RR], a2[RR];
#pragma unroll
        for (int r = 0; r < RR; r++) { a1[r] = 0.f; a2[r] = 0.f; }
        for (int k4 = threadIdx.x * 4; k4 < CT; k4 += 1024) {
            float4 xv = *(const float4*)(xf + k4);
#pragma unroll
            for (int r = 0; r < RR; r++) {
                float4 w1 = *(const float4*)(g_gW1T + r*CT + k4);
                float4 w2 = *(const float4*)(W2 + r*CT + k4);
                a1[r] += xv.x*w1.x + xv.y*w1.y + xv.z*w1.z + xv.w*w1.w;
                a2[r] += xv.x*w2.x + xv.y*w2.y + xv.z*w2.z + xv.w*w2.w;
            }
        }
#pragma unroll
        for (int r = 0; r < RR; r++) {
#pragma unroll
            for (int off = 16; off > 0; off >>= 1) {
                a1[r] += __shfl_down_sync(0xffffffffu, a1[r], off);
                a2[r] += __shfl_down_sync(0xffffffffu, a2[r], off);
            }
        }
        if (lane == 0) {
#pragma unroll
            for (int r = 0; r < RR; r++) { red[warp][r] = a1[r]; red[warp][RR+r] = a2[r]; }
        }
        __syncthreads();
        if (threadIdx.x < 2*RR) {
            float s = 0.f;
#pragma unroll
            for (int w = 0; w < 8; w++) s += red[w][threadIdx.x];
            if (threadIdx.x < RR) g_s1g[(size_t)bn*RR + threadIdx.x] = s;
            else                  g_s2g[((size_t)b*RR + (threadIdx.x - RR))*NN + n] = s;
        }
        __syncthreads();
    }
}

// ------------------------- K5: graph softmax * A_adj (no-max, fp16 out) ----
__global__ void k_gatt_soft(const float* __restrict__ A_adj) {
    int bi = blockIdx.x;
    int b = bi / NN, i = bi - b*NN;
    __shared__ float sc[NN];
    __shared__ float s1r[RR];
    __shared__ float red[256];
    int tid = threadIdx.x;
    if (tid < RR) s1r[tid] = g_s1g[(size_t)(b*NN + i)*RR + tid];
    __syncthreads();
    float scale = rsqrtf((float)CT);
    float lsum = 0.f;
    for (int j = tid; j < NN; j += 256) {
        float s = 0.f;
#pragma unroll
        for (int r = 0; r < RR; r++) s += s1r[r] * g_s2g[(size_t)(b*RR + r)*NN + j];
        float e = expf(s * scale);
        sc[j] = e;
        lsum += e;
    }
    red[tid] = lsum; __syncthreads();
    for (int off = 128; off > 0; off >>= 1) {
        if (tid < off) red[tid] += red[tid + off];
        __syncthreads();
    }
    float inv = 1.f / red[0];
    for (int j = tid; j < NN; j += 256) {
        g_Agh[((size_t)b*NN + i)*NN + j] = __float2half_rn(sc[j] * inv * A_adj[i*NN + j]);
    }
}

// ------------------------- K7: big GEMM g1 = Ag @ x1t (HFMA2, GTK=32) ------
#define GTM 128
#define GTN 128
#define GTK 32
__global__ void __launch_bounds__(256, 2) k_gemm() {
    int b  = blockIdx.z;
    int n0 = blockIdx.y * GTM;
    int j0 = blockIdx.x * GTN;
    const __half* A  = g_Agh + (size_t)b*NN*NN;
    const __half* Bm = g_x1h + (size_t)b*NN*CT;
    float*        Cm = g_g1  + (size_t)b*NN*CT;
    __shared__ __half As[2][GTK][GTM + 8];
    __shared__ __half Bs[2][GTK][GTN + 8];
    int tid = threadIdx.x;
    int tx = tid & 15, ty = tid >> 4;
    int an = tid >> 1, ah = (tid & 1) * 16;    // A: row an, k-offset {0,16}, 2 chunks
    int bk = tid >> 4, bj = (tid & 15) * 8;    // B: rows bk and bk+16
    const uint4 z4 = make_uint4(0u, 0u, 0u, 0u);

    __half2 acch[8][4];
    float accf[8][8];
#pragma unroll
    for (int i = 0; i < 8; i++) {
#pragma unroll
        for (int j = 0; j < 4; j++) acch[i][j] = __float2half2_rn(0.f);
#pragma unroll
        for (int j = 0; j < 8; j++) accf[i][j] = 0.f;
    }

    const int NKT = (NN + GTK - 1) / GTK;      // 32
    {
        int n = n0 + an;
        bool va = (n < NN);                    // k chunks 0..31 all valid at kt=0
        uint4 a0 = va ? *(const uint4*)(A + (size_t)n*NN + ah)     : z4;
        uint4 a1 = va ? *(const uint4*)(A + (size_t)n*NN + ah + 8) : z4;
        const __half* p0 = (const __half*)&a0;
        const __half* p1 = (const __half*)&a1;
#pragma unroll
        for (int i = 0; i < 8; i++) { As[0][ah + i][an] = p0[i]; As[0][ah + 8 + i][an] = p1[i]; }
        *(uint4*)&Bs[0][bk][bj]      = *(const uint4*)(Bm + (size_t)bk*CT + j0 + bj);
        *(uint4*)&Bs[0][bk + 16][bj] = *(const uint4*)(Bm + (size_t)(bk + 16)*CT + j0 + bj);
    }
    __syncthreads();

    for (int kt = 0; kt < NKT; kt++) {
        int buf = kt & 1;
        uint4 a0, a1, b0, b1;
        bool have_next = (kt + 1 < NKT);
        if (have_next) {
            int k0 = (kt + 1) * GTK;
            int n = n0 + an;
            bool v0 = (n < NN) && (k0 + ah < NN);       // 8-aligned chunk validity
            bool v1 = (n < NN) && (k0 + ah + 8 < NN);
            a0 = v0 ? *(const uint4*)(A + (size_t)n*NN + k0 + ah)     : z4;
            a1 = v1 ? *(const uint4*)(A + (size_t)n*NN + k0 + ah + 8) : z4;
            bool vb0 = (k0 + bk < NN);
            bool vb1 = (k0 + bk + 16 < NN);
            b0 = vb0 ? *(const uint4*)(Bm + (size_t)(k0 + bk)*CT + j0 + bj)      : z4;
            b1 = vb1 ? *(const uint4*)(Bm + (size_t)(k0 + bk + 16)*CT + j0 + bj) : z4;
        }
#pragma unroll
        for (int kk = 0; kk < GTK; kk++) {
            uint4 ar = *(const uint4*)&As[buf][kk][ty*8];
            uint4 br = *(const uint4*)&Bs[buf][kk][tx*8];
            const __half*  a8 = (const __half*)&ar;
            const __half2* b2 = (const __half2*)&br;
#pragma unroll
            for (int i = 0; i < 8; i++) {
                __half2 ad = __half2half2(a8[i]);
                acch[i][0] = __hfma2(ad, b2[0], acch[i][0]);
                acch[i][1] = __hfma2(ad, b2[1], acch[i][1]);
                acch[i][2] = __hfma2(ad, b2[2], acch[i][2]);
                acch[i][3] = __hfma2(ad, b2[3], acch[i][3]);
            }
        }
        if ((kt & 1) == 1 || kt == NKT - 1) {  // flush every 64 k-terms -> fp32
#pragma unroll
            for (int i = 0; i < 8; i++)
#pragma unroll
                for (int j = 0; j < 4; j++) {
                    float2 f = __half22float2(acch[i][j]);
                    accf[i][2*j]   += f.x;
                    accf[i][2*j+1] += f.y;
                    acch[i][j] = __float2half2_rn(0.f);
                }
        }
        if (have_next) {
            int nb = buf ^ 1;
            const __half* p0 = (const __half*)&a0;
            const __half* p1 = (const __half*)&a1;
#pragma unroll
            for (int i = 0; i < 8; i++) { As[nb][ah + i][an] = p0[i]; As[nb][ah + 8 + i][an] = p1[i]; }
            *(uint4*)&Bs[nb][bk][bj]      = b0;
            *(uint4*)&Bs[nb][bk + 16][bj] = b1;
        }
        __syncthreads();
    }
#pragma unroll
    for (int i = 0; i < 8; i++) {
        int n = n0 + ty*8 + i;
        if (n < NN) {
            float* cp = Cm + (size_t)n*CT + j0 + tx*8;
            *(float4*)cp       = make_float4(accf[i][0], accf[i][1], accf[i][2], accf[i][3]);
            *(float4*)(cp + 4) = make_float4(accf[i][4], accf[i][5], accf[i][6], accf[i][7]);
        }
    }
}

// ------------------------- K8: temporal-attn projections (r-split, 96 blk) -
__global__ void __launch_bounds__(256) k_tatt_proj() {
    int z  = blockIdx.x;
    int rh = z & 1;
    int bt = z >> 1;
    int b  = bt / 6;
    int tg = bt - b*6;
    int t0 = tg * 4;
    const float* g1b = g_g1 + (size_t)b*NN*CT;
    unsigned long long a1p[2][5], a2p[2][5];
#pragma unroll
    for (int p = 0; p < 2; p++)
#pragma unroll
        for (int r = 0; r < 5; r++) { a1p[p][r] = 0ull; a2p[p][r] = 0ull; }

    for (int i4 = threadIdx.x * 4; i4 < NCO; i4 += 1024) {
        int n = i4 >> 6, c0 = i4 & 63;
        const float* gp = g1b + (size_t)n*CT + c0*TT + t0;
        unsigned long long gq[4][2];
#pragma unroll
        for (int j = 0; j < 4; j++) {
            ulonglong2 gv = *(const ulonglong2*)(gp + j*TT);
            gq[j][0] = gv.x; gq[j][1] = gv.y;
        }
#pragma unroll
        for (int r = 0; r < 5; r++) {
            int rr = rh*5 + r;
            float4 f1 = *(const float4*)(g_F1T + (size_t)rr*NCO + i4);
            float4 f2 = *(const float4*)(g_F2T + (size_t)rr*NCO + i4);
            unsigned long long d;
            d = dup2(f1.x); fma2(a1p[0][r], d, gq[0][0]); fma2(a1p[1][r], d, gq[0][1]);
            d = dup2(f1.y); fma2(a1p[0][r], d, gq[1][0]); fma2(a1p[1][r], d, gq[1][1]);
            d = dup2(f1.z); fma2(a1p[0][r], d, gq[2][0]); fma2(a1p[1][r], d, gq[2][1]);
            d = dup2(f1.w); fma2(a1p[0][r], d, gq[3][0]); fma2(a1p[1][r], d, gq[3][1]);
            d = dup2(f2.x); fma2(a2p[0][r], d, gq[0][0]); fma2(a2p[1][r], d, gq[0][1]);
            d = dup2(f2.y); fma2(a2p[0][r], d, gq[1][0]); fma2(a2p[1][r], d, gq[1][1]);
            d = dup2(f2.z); fma2(a2p[0][r], d, gq[2][0]); fma2(a2p[1][r], d, gq[2][1]);
            d = dup2(f2.w); fma2(a2p[0][r], d, gq[3][0]); fma2(a2p[1][r], d, gq[3][1]);
        }
    }
    __shared__ unsigned long long redu[8][20];
    int lane = threadIdx.x & 31, warp = threadIdx.x >> 5;
#pragma unroll
    for (int p = 0; p < 2; p++)
#pragma unroll
        for (int r = 0; r < 5; r++) {
            unsigned long long v1 = a1p[p][r], v2 = a2p[p][r];
#pragma unroll
            for (int off = 16; off > 0; off >>= 1) {
                float l1 = lo32(v1) + __shfl_down_sync(0xffffffffu, lo32(v1), off);
                float h1 = hi32(v1) + __shfl_down_sync(0xffffffffu, hi32(v1), off);
                float l2 = lo32(v2) + __shfl_down_sync(0xffffffffu, lo32(v2), off);
                float h2 = hi32(v2) + __shfl_down_sync(0xffffffffu, hi32(v2), off);
                v1 = pack2(l1, h1); v2 = pack2(l2, h2);
            }
            if (lane == 0) {
                redu[warp][r*2 + p]      = v1;
                redu[warp][10 + r*2 + p] = v2;
            }
        }
    __syncthreads();
    int tid = threadIdx.x;
    if (tid < 20) {
        float slo = 0.f, shi = 0.f;
#pragma unroll
        for (int w = 0; w < 8; w++) {
            unsigned long long v = redu[w][tid];
            slo += lo32(v); shi += hi32(v);
        }
        int mat = tid / 10;
        int rem = tid - mat*10;
        int r = rem >> 1, p = rem & 1;
        int rr = rh*5 + r;
        int t = t0 + 2*p;
        if (mat == 0) {
            g_s1t[(b*TT + t)*RR + rr]     = slo;
            g_s1t[(b*TT + t + 1)*RR + rr] = shi;
        } else {
            g_s2t[(b*RR + rr)*TT + t]     = slo;
            g_s2t[(b*RR + rr)*TT + t + 1] = shi;
        }
    }
}

// ------------------------- K9: temporal softmax (24x24) --------------------
__global__ void k_tatt_soft() {
    int b = blockIdx.x;
    int i = threadIdx.x;
    if (i >= TT) return;
    float sc[TT];
    float scale = rsqrtf((float)NCO);
#pragma unroll
    for (int j = 0; j < TT; j++) {
        float s = 0.f;
#pragma unroll
        for (int r = 0; r < RR; r++) s += g_s1t[(b*TT + i)*RR + r] * g_s2t[(b*RR + r)*TT + j];
        sc[j] = s * scale;
    }
    float mx = -1e30f;
#pragma unroll
    for (int j = 0; j < TT; j++) mx = fmaxf(mx, sc[j]);
    float sum = 0.f;
#pragma unroll
    for (int j = 0; j < TT; j++) { sc[j] = expf(sc[j] - mx); sum += sc[j]; }
    float inv = 1.f / sum;
#pragma unroll
    for (int j = 0; j < TT; j++) g_attT[(b*TT + i)*TT + j] = sc[j] * inv;
}

// ------------------------- K10: fused mix+tatt+convs (half2) + res+LN (f32) -
__global__ void __launch_bounds__(256) k_final(
        const float* __restrict__ x,
        const float* __restrict__ c1b,
        const float* __restrict__ c2b,
        const float* __restrict__ rb,
        const float* __restrict__ lng,
        const float* __restrict__ lnb,
        float* __restrict__ out) {
    __shared__ float smB[4*CT];
    __shared__ __half at_h[TT*TT];
    __shared__ float mu_s[4][TT], rs_s[4][TT];
    __half* smH = (__half*)smB;
    int blk = blockIdx.x;
    int b = blk / 250;
    int n0 = (blk - b*250) * 4;
    int tid = threadIdx.x;
    int u = tid >> 6, o = tid & 63;
    int n = n0 + u;
    const __half2 hz = __float2half2_rn(0.f);

    {
        const float* src = g_g1 + ((size_t)b*NN + n0)*CT;
        for (int e4 = tid; e4 < CT; e4 += 256) {
            float4 v = *(const float4*)(src + e4*4);
            union { uint2 u2; __half2 h[2]; } q;
            q.h[0] = __floats2half2_rn(v.x, v.y);
            q.h[1] = __floats2half2_rn(v.z, v.w);
            *(uint2*)&smH[e4*4] = q.u2;
        }
    }
    for (int e = tid; e < TT*TT; e += 256) {
        int t = e / TT, tp = e - t*TT;
        at_h[tp*TT + t] = __float2half_rn(g_attT[b*TT*TT + e]);
    }
    __syncthreads();

    __half2 gmp[12];
#pragma unroll
    for (int k = 0; k < 12; k++) gmp[k] = hz;
#pragma unroll 4
    for (int c = 0; c < CC; c++) {
        __half2 wd = __half2half2(g_gWh[c*CC + o]);
        const __half2* pr = (const __half2*)(smH + u*CT + c*TT);
#pragma unroll
        for (int k = 0; k < 12; k++) gmp[k] = __hfma2(wd, pr[k], gmp[k]);
    }

    __half2 x2p[12];
#pragma unroll
    for (int k = 0; k < 12; k++) x2p[k] = hz;
#pragma unroll 4
    for (int tp = 0; tp < TT; tp++) {
        __half gv = (tp & 1) ? __high2half(gmp[tp >> 1]) : __low2half(gmp[tp >> 1]);
        __half2 gd = __half2half2(gv);
        const __half2* ar = (const __half2*)(at_h + tp*TT);
#pragma unroll
        for (int k = 0; k < 12; k++) x2p[k] = __hfma2(gd, ar[k], x2p[k]);
    }
    __syncthreads();
    {
        __half2* wp = (__half2*)(smH + u*CT + o*TT);
#pragma unroll
        for (int k = 0; k < 12; k++) wp[k] = x2p[k];
    }
    __syncthreads();

    __half2 yp[12];
#pragma unroll
    for (int k = 0; k < 12; k++) yp[k] = hz;
#pragma unroll 4
    for (int c = 0; c < CC; c++) {
        const __half2* pr = (const __half2*)(smH + u*CT + c*TT);
        __half2 w0d = __half2half2(g_w1h[c*CC + o]);
        __half2 w1d = __half2half2(g_w1h[CC*CC + c*CC + o]);
        __half2 tp_[12];
#pragma unroll
        for (int k = 0; k < 12; k++) tp_[k] = pr[k];
#pragma unroll
        for (int k = 0; k < 12; k++) yp[k] = __hfma2(w1d, tp_[k], yp[k]);
        __half2 sh = __halves2half2(__float2half_rn(0.f), __low2half(tp_[0]));
        yp[0] = __hfma2(w0d, sh, yp[0]);
#pragma unroll
        for (int k = 1; k < 12; k++) {
            sh = __halves2half2(__high2half(tp_[k-1]), __low2half(tp_[k]));
            yp[k] = __hfma2(w0d, sh, yp[k]);
        }
    }
    __half2 y1h[12];
    {
        float b1 = __ldg(c1b + o);
#pragma unroll
        for (int k = 0; k < 12; k++) {
            float2 f = __half22float2(yp[k]);
            y1h[k] = __floats2half2_rn(fmaxf(f.x + b1, 0.f), fmaxf(f.y + b1, 0.f));
        }
    }
    __syncthreads();
    {
        __half2* wp = (__half2*)(smH + u*CT + o*TT);
#pragma unroll
        for (int k = 0; k < 12; k++) wp[k] = y1h[k];
    }
    __syncthreads();

    __half2 vph[12];
#pragma unroll
    for (int k = 0; k < 12; k++) vph[k] = hz;
#pragma unroll 4
    for (int c = 0; c < CC; c++) {
        const __half2* pr = (const __half2*)(smH + u*CT + c*TT);
        __half2 w0d = __half2half2(g_w2h[c*CC + o]);
        __half2 w1d = __half2half2(g_w2h[CC*CC + c*CC + o]);
        __half2 prev = hz;
#pragma unroll
        for (int k = 0; k < 12; k++) {
            __half2 cur = pr[k];
            vph[k] = __hfma2(w1d, cur, vph[k]);
            vph[k] = __hfma2(w0d, prev, vph[k]);
            prev = cur;
        }
    }
    float v[TT];
    {
        float b2 = __ldg(c2b + o);
#pragma unroll
        for (int k = 0; k < 12; k++) {
            float2 f = __half22float2(vph[k]);
            v[2*k]   = fmaxf(f.x + b2, 0.f);
            v[2*k+1] = fmaxf(f.y + b2, 0.f);
        }
    }
    __syncthreads();

    for (int e4 = tid; e4 < CT; e4 += 256) {
        int f = e4 * 4;
        int u2 = f / CT, rem = f - u2*CT;
        int c = rem / TT, t = rem - c*TT;
        *(float4*)&smB[f] = *(const float4*)(x + (size_t)((b*CC + c)*NN + n0 + u2)*TT + t);
    }
    __syncthreads();

    unsigned long long vp[12];
#pragma unroll
    for (int k = 0; k < 12; k++) vp[k] = pack2(v[2*k], v[2*k+1]);
#pragma unroll 4
    for (int c = 0; c < CC; c++) {
        const unsigned long long* pr = (const unsigned long long*)&smB[u*CT + c*TT];
        unsigned long long rwd = dup2(__ldg(g_rT + c*CC + o));
#pragma unroll
        for (int k = 0; k < 12; k++) fma2(vp[k], rwd, pr[k]);
    }
    {
        float biasr = __ldg(rb + o);
#pragma unroll
        for (int k = 0; k < 12; k++) {
            float lo = fmaxf(lo32(vp[k]) + biasr, 0.f);
            float hi = fmaxf(hi32(vp[k]) + biasr, 0.f);
            v[2*k] = lo; v[2*k+1] = hi;
        }
    }
    __syncthreads();

    {
        float* wp = &smB[u*CT + o*TT];
#pragma unroll
        for (int k = 0; k < 6; k++)
            *(float4*)(wp + 4*k) = make_float4(v[4*k], v[4*k+1], v[4*k+2], v[4*k+3]);
    }
    __syncthreads();
    if (tid < 96) {
        int ur = tid / TT, tr = tid - ur*TT;
        float S = 0.f, Q = 0.f;
#pragma unroll 8
        for (int oo = 0; oo < CC; oo++) {
            float val = smB[ur*CT + oo*TT + tr];
            S += val; Q += val*val;
        }
        float mu = S * (1.f/CC);
        float var = Q * (1.f/CC) - mu*mu;
        mu_s[ur][tr] = mu;
        rs_s[ur][tr] = rsqrtf(var + 1e-5f);
    }
    __syncthreads();
    {
        float gmul = __ldg(lng + o), badd = __ldg(lnb + o);
        float* op = out + (size_t)((b*CC + o)*NN + n)*TT;
        float res[TT];
#pragma unroll
        for (int t = 0; t < TT; t++)
            res[t] = (v[t] - mu_s[u][t]) * rs_s[u][t] * gmul + badd;
#pragma unroll
        for (int k = 0; k < 6; k++)
            *(float4*)(op + 4*k) = make_float4(res[4*k], res[4*k+1], res[4*k+2], res[4*k+3]);
    }
}

// ------------------------- launch ------------------------------------------
extern "C" void kernel_launch(void* const* d_in, const int* in_sizes, int n_in,
                              void* d_out, int out_size) {
    const float* x     = (const float*)d_in[0];
    const float* A_adj = (const float*)d_in[1];
    const float* a0W1  = (const float*)d_in[2];
    const float* a0W2  = (const float*)d_in[3];
    const float* gW1   = (const float*)d_in[4];
    const float* gW2   = (const float*)d_in[5];
    const float* gcnW  = (const float*)d_in[6];
    const float* tW1   = (const float*)d_in[7];
    const float* tW2   = (const float*)d_in[8];
    const float* c1w   = (const float*)d_in[9];
    const float* c1b   = (const float*)d_in[10];
    const float* c2w   = (const float*)d_in[11];
    const float* c2b   = (const float*)d_in[12];
    const float* resw  = (const float*)d_in[13];
    const float* resb  = (const float*)d_in[14];
    const float* lng   = (const float*)d_in[15];
    const float* lnb   = (const float*)d_in[16];
    float* out = (float*)d_out;

    k_prep<<<1014, 256>>>(a0W1, gW1, c1w, c2w, resw, gcnW);
    k_fuse<<<NN, 256>>>(gcnW, tW1, tW2);
    k_attA_proj<<<BB*CC/4, 256>>>(x, a0W2);
    k_attA_soft<<<BB*CC, CC>>>();
    k_chan_apply<<<dim3(NT/64, BB), 256>>>(x);
    k_gatt_proj<<<BB*NN/16, 256>>>(gW2);
    k_gatt_soft<<<BB*NN, 256>>>(A_adj);
    k_gemm<<<dim3(CT/GTN, (NN + GTM - 1)/GTM, BB), 256>>>();
    k_tatt_proj<<<BB*6*2, 256>>>();
    k_tatt_soft<<<BB, 32>>>();
    k_final<<<BB*NN/4, 256>>>(x, c1b, c2b, resb, lng, lnb, out);
}